// round 10
// baseline (speedup 1.0000x reference)
#include <cuda_runtime.h>
#include <cuda_bf16.h>
#include <cstdint>

#define BH    16
#define LSEQ  2048
#define DDIM  64
#define NELEM (BH * LSEQ * DDIM)       // 2,097,152 per tensor
#define SBF   72                        // bf16 smem row stride (144B, ldmatrix conflict-free)
#define TSZ   (64 * SBF)                // one 64x64 tile in smem (bf16 elems)
#define KEXP  0.18033688011112042f      // 0.125 * log2(e)

// bf16 split-precision copies of Q,K,V (static device scratch — allowed)
__device__ __nv_bfloat16 gH[3][NELEM];
__device__ __nv_bfloat16 gL[3][NELEM];

// ---------------------------------------------------------------- helpers ----
__device__ __forceinline__ uint32_t s2u(const void* p) {
    return (uint32_t)__cvta_generic_to_shared(p);
}
__device__ __forceinline__ float fexp2(float x) {
    float r; asm("ex2.approx.ftz.f32 %0, %1;" : "=f"(r) : "f"(x)); return r;
}
__device__ __forceinline__ void ldsmx4(uint32_t r[4], uint32_t a) {
    asm volatile("ldmatrix.sync.aligned.m8n8.x4.shared.b16 {%0,%1,%2,%3}, [%4];"
                 : "=r"(r[0]), "=r"(r[1]), "=r"(r[2]), "=r"(r[3]) : "r"(a));
}
__device__ __forceinline__ void ldsmx4t(uint32_t r[4], uint32_t a) {
    asm volatile("ldmatrix.sync.aligned.m8n8.x4.trans.shared.b16 {%0,%1,%2,%3}, [%4];"
                 : "=r"(r[0]), "=r"(r[1]), "=r"(r[2]), "=r"(r[3]) : "r"(a));
}
__device__ __forceinline__ void mma_bf16(float c[4], const uint32_t a[4], const uint32_t b[2]) {
    asm volatile("mma.sync.aligned.m16n8k16.row.col.f32.bf16.bf16.f32 "
                 "{%0,%1,%2,%3}, {%4,%5,%6,%7}, {%8,%9}, {%0,%1,%2,%3};"
                 : "+f"(c[0]), "+f"(c[1]), "+f"(c[2]), "+f"(c[3])
                 : "r"(a[0]), "r"(a[1]), "r"(a[2]), "r"(a[3]), "r"(b[0]), "r"(b[1]));
}
__device__ __forceinline__ void splitpack(float a, float b, uint32_t& hi, uint32_t& lo) {
    __nv_bfloat162 h = __floats2bfloat162_rn(a, b);
    float2 f = __bfloat1622float2(h);
    __nv_bfloat162 l2 = __floats2bfloat162_rn(a - f.x, b - f.y);
    hi = *reinterpret_cast<uint32_t*>(&h);
    lo = *reinterpret_cast<uint32_t*>(&l2);
}

// ---- cp.async staging: 64x64 bf16 tile, gmem stride 64 -> smem stride SBF ----
__device__ __forceinline__ void cp16(uint32_t d, const void* s) {
    asm volatile("cp.async.cg.shared.global [%0], [%1], 16;" :: "r"(d), "l"(s));
}
__device__ __forceinline__ void stage_async(__nv_bfloat16* dst, const __nv_bfloat16* src, int t) {
    int r = t >> 1, cb = (t & 1) * 32;
    const __nv_bfloat16* s = src + r * DDIM + cb;
    uint32_t d = s2u(dst + r * SBF + cb);
    cp16(d, s); cp16(d + 16, s + 8); cp16(d + 32, s + 16); cp16(d + 48, s + 24);
}
#define CP_COMMIT() asm volatile("cp.async.commit_group;")
#define CP_WAIT(n)  asm volatile("cp.async.wait_group %0;" :: "n"(n))

// ============================== gemm64: 16 rows x 64 cols per warp (flash) ====
__device__ __forceinline__ void gemm64(float c[8][4],
    const __nv_bfloat16* Ah, const __nv_bfloat16* Al, int r0,
    const __nv_bfloat16* Bh, const __nv_bfloat16* Bl, int lane)
{
    #pragma unroll
    for (int nt = 0; nt < 8; nt++) { c[nt][0]=0.f; c[nt][1]=0.f; c[nt][2]=0.f; c[nt][3]=0.f; }
    const int aoff = (r0 + (lane & 15)) * SBF + ((lane >> 4) << 3);
    const int boff = ((lane & 7) + ((lane >> 4) << 3)) * SBF + (((lane >> 3) & 1) << 3);
    #pragma unroll
    for (int kt = 0; kt < 4; kt++) {
        uint32_t ah[4], al[4];
        ldsmx4(ah, s2u(Ah + aoff + kt * 16));
        ldsmx4(al, s2u(Al + aoff + kt * 16));
        #pragma unroll
        for (int np = 0; np < 4; np++) {
            uint32_t bh[4], bl[4];
            ldsmx4(bh, s2u(Bh + boff + np * 16 * SBF + kt * 16));
            ldsmx4(bl, s2u(Bl + boff + np * 16 * SBF + kt * 16));
            mma_bf16(c[2*np],   ah, bh);  mma_bf16(c[2*np+1], ah, bh + 2);
            mma_bf16(c[2*np],   al, bh);  mma_bf16(c[2*np+1], al, bh + 2);
            mma_bf16(c[2*np],   ah, bl);  mma_bf16(c[2*np+1], ah, bl + 2);
        }
    }
}

// ====================== gemm32: 32 rows x 32 cols per warp (weights, 2x2) =====
// Full 3-term split: ah*bh + al*bh + ah*bl.  (2-term variant failed rel-err in R7:
// denominator/numerator asymmetry — do NOT reintroduce.)
__device__ __forceinline__ void gemm32(float c[2][4][4],
    const __nv_bfloat16* Ah, const __nv_bfloat16* Al, int wr,
    const __nv_bfloat16* Bh, const __nv_bfloat16* Bl, int wc, int lane)
{
    #pragma unroll
    for (int mi = 0; mi < 2; mi++)
        #pragma unroll
        for (int nj = 0; nj < 4; nj++)
            { c[mi][nj][0]=0.f; c[mi][nj][1]=0.f; c[mi][nj][2]=0.f; c[mi][nj][3]=0.f; }
    const int aoff = (32 * wr + (lane & 15)) * SBF + ((lane >> 4) << 3);
    const int boff = (32 * wc + (lane & 7) + ((lane >> 4) << 3)) * SBF + (((lane >> 3) & 1) << 3);
    #pragma unroll
    for (int kt = 0; kt < 4; kt++) {
        uint32_t ah0[4], al0[4], ah1[4], al1[4];
        ldsmx4(ah0, s2u(Ah + aoff + kt * 16));
        ldsmx4(al0, s2u(Al + aoff + kt * 16));
        ldsmx4(ah1, s2u(Ah + aoff + 16 * SBF + kt * 16));
        ldsmx4(al1, s2u(Al + aoff + 16 * SBF + kt * 16));
        #pragma unroll
        for (int np = 0; np < 2; np++) {
            uint32_t bh[4], bl[4];
            ldsmx4(bh, s2u(Bh + boff + np * 16 * SBF + kt * 16));
            ldsmx4(bl, s2u(Bl + boff + np * 16 * SBF + kt * 16));
            mma_bf16(c[0][2*np],   ah0, bh);  mma_bf16(c[0][2*np+1], ah0, bh + 2);
            mma_bf16(c[0][2*np],   al0, bh);  mma_bf16(c[0][2*np+1], al0, bh + 2);
            mma_bf16(c[0][2*np],   ah0, bl);  mma_bf16(c[0][2*np+1], ah0, bl + 2);
            mma_bf16(c[1][2*np],   ah1, bh);  mma_bf16(c[1][2*np+1], ah1, bh + 2);
            mma_bf16(c[1][2*np],   al1, bh);  mma_bf16(c[1][2*np+1], al1, bh + 2);
            mma_bf16(c[1][2*np],   ah1, bl);  mma_bf16(c[1][2*np+1], ah1, bl + 2);
        }
    }
}

// -------------------------------------------------------------- prep kernel --
__global__ void prep_kernel(const float* __restrict__ Q,
                            const float* __restrict__ K,
                            const float* __restrict__ V) {
    int i4 = blockIdx.x * 256 + threadIdx.x;     // quad index
    const float* s = blockIdx.y == 0 ? Q : (blockIdx.y == 1 ? K : V);
    float4 x = ((const float4*)s)[i4];
    __nv_bfloat162 h0 = __floats2bfloat162_rn(x.x, x.y);
    __nv_bfloat162 h1 = __floats2bfloat162_rn(x.z, x.w);
    float2 f0 = __bfloat1622float2(h0);
    float2 f1 = __bfloat1622float2(h1);
    __nv_bfloat162 l0 = __floats2bfloat162_rn(x.x - f0.x, x.y - f0.y);
    __nv_bfloat162 l1 = __floats2bfloat162_rn(x.z - f1.x, x.w - f1.y);
    ((uint2*)&gH[blockIdx.y][0])[i4] = make_uint2(*(uint32_t*)&h0, *(uint32_t*)&h1);
    ((uint2*)&gL[blockIdx.y][0])[i4] = make_uint2(*(uint32_t*)&l0, *(uint32_t*)&l1);
}

// -------------------------------------------------------------- flash (mma) --
// out = softmax(Q K^T / 8) V.  No max-subtraction. Double-buffered cp.async.
__global__ __launch_bounds__(128, 2)
void flash_mma(float* __restrict__ out)
{
    extern __shared__ __nv_bfloat16 sb[];
    __nv_bfloat16* sQh = sb;
    __nv_bfloat16* sQl = sb + TSZ;
    __nv_bfloat16* strm = sb + 2 * TSZ;          // 2 buffers x {Kh,Kl,Vh,Vl}

    const int t = threadIdx.x, w = t >> 5, lane = t & 31;
    const int head = blockIdx.y;
    const int row0 = blockIdx.x * 64;
    const size_t hoff = (size_t)head * LSEQ * DDIM;

    const __nv_bfloat16 *gQH = &gH[0][0], *gQL = &gL[0][0];
    const __nv_bfloat16 *gKH = &gH[1][0], *gKL = &gL[1][0];
    const __nv_bfloat16 *gVH = &gH[2][0], *gVL = &gL[2][0];

    // stage Q (group), prefetch chunk 0 (group)
    stage_async(sQh, gQH + hoff + (size_t)row0 * DDIM, t);
    stage_async(sQl, gQL + hoff + (size_t)row0 * DDIM, t);
    CP_COMMIT();
    {
        __nv_bfloat16* b0 = strm;
        stage_async(b0,           gKH + hoff, t);
        stage_async(b0 + TSZ,     gKL + hoff, t);
        stage_async(b0 + 2 * TSZ, gVH + hoff, t);
        stage_async(b0 + 3 * TSZ, gVL + hoff, t);
    }
    CP_COMMIT();

    float o[8][4];
    #pragma unroll
    for (int nt = 0; nt < 8; nt++) { o[nt][0]=0.f; o[nt][1]=0.f; o[nt][2]=0.f; o[nt][3]=0.f; }
    float rs0 = 0.f, rs1 = 0.f;
    const int vbase = (lane & 15) * SBF + ((lane >> 4) << 3);

    for (int ch = 0; ch < LSEQ / 64; ch++) {
        if (ch + 1 < LSEQ / 64) {
            size_t coff = hoff + (size_t)(ch + 1) * 64 * DDIM;
            __nv_bfloat16* nb = strm + ((ch + 1) & 1) * 4 * TSZ;
            stage_async(nb,           gKH + coff, t);
            stage_async(nb + TSZ,     gKL + coff, t);
            stage_async(nb + 2 * TSZ, gVH + coff, t);
            stage_async(nb + 3 * TSZ, gVL + coff, t);
            CP_COMMIT(); CP_WAIT(1);
        } else CP_WAIT(0);
        __syncthreads();

        __nv_bfloat16* cb = strm + (ch & 1) * 4 * TSZ;
        __nv_bfloat16 *sKh = cb, *sKl = cb + TSZ, *sVh = cb + 2 * TSZ, *sVl = cb + 3 * TSZ;

        float c[8][4];
        gemm64(c, sQh, sQl, 16 * w, sKh, sKl, lane);

        float p[8][4];
        #pragma unroll
        for (int nt = 0; nt < 8; nt++) {
            p[nt][0] = fexp2(c[nt][0] * KEXP);
            p[nt][1] = fexp2(c[nt][1] * KEXP);
            p[nt][2] = fexp2(c[nt][2] * KEXP);
            p[nt][3] = fexp2(c[nt][3] * KEXP);
            rs0 += p[nt][0] + p[nt][1];
            rs1 += p[nt][2] + p[nt][3];
        }

        #pragma unroll
        for (int kt = 0; kt < 4; kt++) {
            uint32_t pha[4], pla[4];
            splitpack(p[2*kt][0],   p[2*kt][1],   pha[0], pla[0]);
            splitpack(p[2*kt][2],   p[2*kt][3],   pha[1], pla[1]);
            splitpack(p[2*kt+1][0], p[2*kt+1][1], pha[2], pla[2]);
            splitpack(p[2*kt+1][2], p[2*kt+1][3], pha[3], pla[3]);
            #pragma unroll
            for (int np = 0; np < 4; np++) {
                uint32_t vh[4], vl[4];
                ldsmx4t(vh, s2u(sVh + vbase + kt * 16 * SBF + np * 16));
                ldsmx4t(vl, s2u(sVl + vbase + kt * 16 * SBF + np * 16));
                mma_bf16(o[2*np],   pha, vh);  mma_bf16(o[2*np+1], pha, vh + 2);
                mma_bf16(o[2*np],   pla, vh);  mma_bf16(o[2*np+1], pla, vh + 2);
                mma_bf16(o[2*np],   pha, vl);  mma_bf16(o[2*np+1], pha, vl + 2);
            }
        }
        __syncthreads();
    }

    rs0 += __shfl_xor_sync(~0u, rs0, 1); rs0 += __shfl_xor_sync(~0u, rs0, 2);
    rs1 += __shfl_xor_sync(~0u, rs1, 1); rs1 += __shfl_xor_sync(~0u, rs1, 2);
    const float inv0 = 1.0f / rs0, inv1 = 1.0f / rs1;

    const int r0 = row0 + 16 * w + (lane >> 2);
    float* O0 = out + ((size_t)head * LSEQ + r0) * DDIM + 2 * (lane & 3);
    float* O1 = O0 + 8 * DDIM;
    #pragma unroll
    for (int nt = 0; nt < 8; nt++) {
        *(float2*)(O0 + nt * 8) = make_float2(o[nt][0] * inv0, o[nt][1] * inv0);
        *(float2*)(O1 + nt * 8) = make_float2(o[nt][2] * inv1, o[nt][3] * inv1);
    }
}

// ------------------------------------------------------------ weights (mma) --
// outw = softmax(Q Q^T / 8) + softmax(K K^T / 8).
// Warp (wr,wc) = 32 rows x 32 cols of the 64x64 CTA tile.
// Pass 1: row sums of exp (3-term scores, identical to pass 2 — required for
// numerator/denominator cancellation). Jobs Q0..Q31,K0..K31, double-buffered.
// Pass 2: recompute, jobs (Qch,Kch) alternating, write sum once.
__global__ __launch_bounds__(128, 2)
void weights_mma(float* __restrict__ outw)
{
    extern __shared__ __nv_bfloat16 sb[];
    __nv_bfloat16* sAh = sb;                 // Q rows (persist)
    __nv_bfloat16* sAl = sb + TSZ;
    __nv_bfloat16* sBh = sb + 2 * TSZ;       // K rows (persist)
    __nv_bfloat16* sBl = sb + 3 * TSZ;
    __nv_bfloat16* sCh[2] = { sb + 4 * TSZ, sb + 6 * TSZ };
    __nv_bfloat16* sCl[2] = { sb + 5 * TSZ, sb + 7 * TSZ };
    float* red = (float*)(sb + 8 * TSZ);     // redQ[64][2], redK[64][2]

    const int t = threadIdx.x, w = t >> 5, lane = t & 31;
    const int wr = w & 1, wc = w >> 1;
    const int head = blockIdx.y;
    const int row0 = blockIdx.x * 64;
    const size_t hoff = (size_t)head * LSEQ * DDIM;
    const size_t roff = hoff + (size_t)row0 * DDIM;

    const __nv_bfloat16 *gQH = &gH[0][0], *gQL = &gL[0][0];
    const __nv_bfloat16 *gKH = &gH[1][0], *gKL = &gL[1][0];

    // persist tiles (group), then job0 = Q chunk 0 (group)
    stage_async(sAh, gQH + roff, t);
    stage_async(sAl, gQL + roff, t);
    stage_async(sBh, gKH + roff, t);
    stage_async(sBl, gKL + roff, t);
    CP_COMMIT();
    stage_async(sCh[0], gQH + hoff, t);
    stage_async(sCl[0], gQL + hoff, t);
    CP_COMMIT();

    float sq[2][2] = {{0.f,0.f},{0.f,0.f}}, sk[2][2] = {{0.f,0.f},{0.f,0.f}};

    // ---------------- pass 1: row sums (3-term) ----------------
    for (int j = 0; j < 64; j++) {
        int jn = j + 1;
        if (jn < 64) {
            size_t off = hoff + (size_t)(jn & 31) * 64 * DDIM;
            stage_async(sCh[jn & 1], (jn < 32 ? gQH : gKH) + off, t);
            stage_async(sCl[jn & 1], (jn < 32 ? gQL : gKL) + off, t);
            CP_COMMIT(); CP_WAIT(1);
        } else CP_WAIT(0);
        __syncthreads();

        float c[2][4][4];
        if (j < 32) {
            gemm32(c, sAh, sAl, wr, sCh[j & 1], sCl[j & 1], wc, lane);
            #pragma unroll
            for (int mi = 0; mi < 2; mi++)
                #pragma unroll
                for (int nj = 0; nj < 4; nj++) {
                    sq[mi][0] += fexp2(c[mi][nj][0] * KEXP) + fexp2(c[mi][nj][1] * KEXP);
                    sq[mi][1] += fexp2(c[mi][nj][2] * KEXP) + fexp2(c[mi][nj][3] * KEXP);
                }
        } else {
            gemm32(c, sBh, sBl, wr, sCh[j & 1], sCl[j & 1], wc, lane);
            #pragma unroll
            for (int mi = 0; mi < 2; mi++)
                #pragma unroll
                for (int nj = 0; nj < 4; nj++) {
                    sk[mi][0] += fexp2(c[mi][nj][0] * KEXP) + fexp2(c[mi][nj][1] * KEXP);
                    sk[mi][1] += fexp2(c[mi][nj][2] * KEXP) + fexp2(c[mi][nj][3] * KEXP);
                }
        }
        __syncthreads();
    }

    // prefetch pass-2 job0 (Q chunk 0) while reducing sums
    stage_async(sCh[0], gQH + hoff, t);
    stage_async(sCl[0], gQL + hoff, t);
    CP_COMMIT();

    // combine: quad shuffle (cols within warp), then cross-warp (wc) via smem
    #pragma unroll
    for (int mi = 0; mi < 2; mi++)
        #pragma unroll
        for (int b = 0; b < 2; b++) {
            float x = sq[mi][b];
            x += __shfl_xor_sync(~0u, x, 1); x += __shfl_xor_sync(~0u, x, 2);
            sq[mi][b] = x;
            float y = sk[mi][b];
            y += __shfl_xor_sync(~0u, y, 1); y += __shfl_xor_sync(~0u, y, 2);
            sk[mi][b] = y;
        }
    if ((lane & 3) == 0) {
        #pragma unroll
        for (int mi = 0; mi < 2; mi++)
            #pragma unroll
            for (int b = 0; b < 2; b++) {
                int rl = 32 * wr + 16 * mi + (lane >> 2) + 8 * b;
                red[rl * 2 + wc]       = sq[mi][b];
                red[128 + rl * 2 + wc] = sk[mi][b];
            }
    }
    __syncthreads();
    float iq[2][2], ik[2][2];
    #pragma unroll
    for (int mi = 0; mi < 2; mi++)
        #pragma unroll
        for (int b = 0; b < 2; b++) {
            int rl = 32 * wr + 16 * mi + (lane >> 2) + 8 * b;
            iq[mi][b] = 1.0f / (red[rl * 2] + red[rl * 2 + 1]);
            ik[mi][b] = 1.0f / (red[128 + rl * 2] + red[128 + rl * 2 + 1]);
        }

    // ---------------- pass 2: recompute + write ----------------
    float pq[2][4][4];
    float* O = outw + (size_t)head * LSEQ * LSEQ;
    const int colb = 32 * wc + 2 * (lane & 3);

    for (int j = 0; j < 64; j++) {
        const int ch = j >> 1, mat = j & 1;
        int jn = j + 1;
        if (jn < 64) {
            const int ch2 = jn >> 1, mat2 = jn & 1;
            size_t off = hoff + (size_t)ch2 * 64 * DDIM;
            stage_async(sCh[jn & 1], (mat2 ? gKH : gQH) + off, t);
            stage_async(sCl[jn & 1], (mat2 ? gKL : gQL) + off, t);
            CP_COMMIT(); CP_WAIT(1);
        } else CP_WAIT(0);
        __syncthreads();

        float c[2][4][4];
        gemm32(c, mat ? sBh : sAh, mat ? sBl : sAl, wr, sCh[j & 1], sCl[j & 1], wc, lane);

        if (!mat) {
            #pragma unroll
            for (int mi = 0; mi < 2; mi++)
                #pragma unroll
                for (int nj = 0; nj < 4; nj++) {
                    pq[mi][nj][0] = fexp2(c[mi][nj][0] * KEXP) * iq[mi][0];
                    pq[mi][nj][1] = fexp2(c[mi][nj][1] * KEXP) * iq[mi][0];
                    pq[mi][nj][2] = fexp2(c[mi][nj][2] * KEXP) * iq[mi][1];
                    pq[mi][nj][3] = fexp2(c[mi][nj][3] * KEXP) * iq[mi][1];
                }
        } else {
            #pragma unroll
            for (int mi = 0; mi < 2; mi++) {
                int r_ = row0 + 32 * wr + 16 * mi + (lane >> 2);
                float* W0 = O + (size_t)r_ * LSEQ + ch * 64 + colb;
                float* W1 = W0 + 8 * LSEQ;
                #pragma unroll
                for (int nj = 0; nj < 4; nj++) {
                    float f0 = pq[mi][nj][0] + fexp2(c[mi][nj][0] * KEXP) * ik[mi][0];
                    float f1 = pq[mi][nj][1] + fexp2(c[mi][nj][1] * KEXP) * ik[mi][0];
                    float f2 = pq[mi][nj][2] + fexp2(c[mi][nj][2] * KEXP) * ik[mi][1];
                    float f3 = pq[mi][nj][3] + fexp2(c[mi][nj][3] * KEXP) * ik[mi][1];
                    *(float2*)(W0 + 8 * nj) = make_float2(f0, f1);
                    *(float2*)(W1 + 8 * nj) = make_float2(f2, f3);
                }
            }
        }
        __syncthreads();
    }
}

// ------------------------------------------------------------------ launcher --
extern "C" void kernel_launch(void* const* d_in, const int* in_sizes, int n_in,
                              void* d_out, int out_size) {
    const float* Q = (const float*)d_in[0];
    const float* K = (const float*)d_in[1];
    const float* V = (const float*)d_in[2];
    float* out = (float*)d_out;

    const int F_SMEM = 10 * TSZ * 2;                 // 92,160 B
    const int W_SMEM = 8 * TSZ * 2 + 256 * 4;        // 74,752 B

    cudaFuncSetAttribute(flash_mma,   cudaFuncAttributeMaxDynamicSharedMemorySize, F_SMEM);
    cudaFuncSetAttribute(weights_mma, cudaFuncAttributeMaxDynamicSharedMemorySize, W_SMEM);

    prep_kernel<<<dim3(NELEM / 1024, 3), 256>>>(Q, K, V);
    flash_mma<<<dim3(LSEQ / 64, BH), 128, F_SMEM>>>(out);

    const size_t outElems  = (size_t)NELEM;
    const size_t attnElems = (size_t)BH * LSEQ * LSEQ;
    if ((size_t)out_size >= outElems + attnElems) {
        weights_mma<<<dim3(LSEQ / 64, BH), 128, W_SMEM>>>(out + outElems);
    }
}

// round 12
// speedup vs baseline: 1.0768x; 1.0768x over previous
#include <cuda_runtime.h>
#include <cuda_bf16.h>
#include <cstdint>

#define BH    16
#define LSEQ  2048
#define DDIM  64
#define NELEM (BH * LSEQ * DDIM)       // 2,097,152 per tensor
#define SBF   72                        // bf16 smem row stride (144B, ldmatrix conflict-free)
#define TSZ   (64 * SBF)
#define KEXP  0.18033688011112042f      // 0.125 * log2(e)
#define ATTN  (BH * LSEQ * LSEQ)        // 67,108,864

// static device scratch (allowed): bf16 splits + exp scratch + row inverses
__device__ __nv_bfloat16 gH[3][NELEM];
__device__ __nv_bfloat16 gL[3][NELEM];
__device__ float gScr[2][ATTN];         // exp(QQ^T/8), exp(KK^T/8)
__device__ float gInv[2][BH * LSEQ];    // 1/rowsum for each matrix

// ---------------------------------------------------------------- helpers ----
__device__ __forceinline__ uint32_t s2u(const void* p) {
    return (uint32_t)__cvta_generic_to_shared(p);
}
__device__ __forceinline__ float fexp2(float x) {
    float r; asm("ex2.approx.ftz.f32 %0, %1;" : "=f"(r) : "f"(x)); return r;
}
__device__ __forceinline__ void ldsmx4(uint32_t r[4], uint32_t a) {
    asm volatile("ldmatrix.sync.aligned.m8n8.x4.shared.b16 {%0,%1,%2,%3}, [%4];"
                 : "=r"(r[0]), "=r"(r[1]), "=r"(r[2]), "=r"(r[3]) : "r"(a));
}
__device__ __forceinline__ void ldsmx4t(uint32_t r[4], uint32_t a) {
    asm volatile("ldmatrix.sync.aligned.m8n8.x4.trans.shared.b16 {%0,%1,%2,%3}, [%4];"
                 : "=r"(r[0]), "=r"(r[1]), "=r"(r[2]), "=r"(r[3]) : "r"(a));
}
__device__ __forceinline__ void mma_bf16(float c[4], const uint32_t a[4], const uint32_t b[2]) {
    asm volatile("mma.sync.aligned.m16n8k16.row.col.f32.bf16.bf16.f32 "
                 "{%0,%1,%2,%3}, {%4,%5,%6,%7}, {%8,%9}, {%0,%1,%2,%3};"
                 : "+f"(c[0]), "+f"(c[1]), "+f"(c[2]), "+f"(c[3])
                 : "r"(a[0]), "r"(a[1]), "r"(a[2]), "r"(a[3]), "r"(b[0]), "r"(b[1]));
}
__device__ __forceinline__ void splitpack(float a, float b, uint32_t& hi, uint32_t& lo) {
    __nv_bfloat162 h = __floats2bfloat162_rn(a, b);
    float2 f = __bfloat1622float2(h);
    __nv_bfloat162 l2 = __floats2bfloat162_rn(a - f.x, b - f.y);
    hi = *reinterpret_cast<uint32_t*>(&h);
    lo = *reinterpret_cast<uint32_t*>(&l2);
}

// ---- cp.async staging ----
__device__ __forceinline__ void cp16(uint32_t d, const void* s) {
    asm volatile("cp.async.cg.shared.global [%0], [%1], 16;" :: "r"(d), "l"(s));
}
__device__ __forceinline__ void stage_async(__nv_bfloat16* dst, const __nv_bfloat16* src, int t) {
    int r = t >> 1, cb = (t & 1) * 32;
    const __nv_bfloat16* s = src + r * DDIM + cb;
    uint32_t d = s2u(dst + r * SBF + cb);
    cp16(d, s); cp16(d + 16, s + 8); cp16(d + 32, s + 16); cp16(d + 48, s + 24);
}
#define CP_COMMIT() asm volatile("cp.async.commit_group;")
#define CP_WAIT(n)  asm volatile("cp.async.wait_group %0;" :: "n"(n))

// ============================== gemm64 (flash) ================================
__device__ __forceinline__ void gemm64(float c[8][4],
    const __nv_bfloat16* Ah, const __nv_bfloat16* Al, int r0,
    const __nv_bfloat16* Bh, const __nv_bfloat16* Bl, int lane)
{
    #pragma unroll
    for (int nt = 0; nt < 8; nt++) { c[nt][0]=0.f; c[nt][1]=0.f; c[nt][2]=0.f; c[nt][3]=0.f; }
    const int aoff = (r0 + (lane & 15)) * SBF + ((lane >> 4) << 3);
    const int boff = ((lane & 7) + ((lane >> 4) << 3)) * SBF + (((lane >> 3) & 1) << 3);
    #pragma unroll
    for (int kt = 0; kt < 4; kt++) {
        uint32_t ah[4], al[4];
        ldsmx4(ah, s2u(Ah + aoff + kt * 16));
        ldsmx4(al, s2u(Al + aoff + kt * 16));
        #pragma unroll
        for (int np = 0; np < 4; np++) {
            uint32_t bh[4], bl[4];
            ldsmx4(bh, s2u(Bh + boff + np * 16 * SBF + kt * 16));
            ldsmx4(bl, s2u(Bl + boff + np * 16 * SBF + kt * 16));
            mma_bf16(c[2*np],   ah, bh);  mma_bf16(c[2*np+1], ah, bh + 2);
            mma_bf16(c[2*np],   al, bh);  mma_bf16(c[2*np+1], al, bh + 2);
            mma_bf16(c[2*np],   ah, bl);  mma_bf16(c[2*np+1], ah, bl + 2);
        }
    }
}

// ============================== gemm32 (weights, 2x2 warp tile) ===============
// Full 3-term split (2-term failed rel-err in R7 — numerator/denominator must
// use identical score math).
__device__ __forceinline__ void gemm32(float c[2][4][4],
    const __nv_bfloat16* Ah, const __nv_bfloat16* Al, int wr,
    const __nv_bfloat16* Bh, const __nv_bfloat16* Bl, int wc, int lane)
{
    #pragma unroll
    for (int mi = 0; mi < 2; mi++)
        #pragma unroll
        for (int nj = 0; nj < 4; nj++)
            { c[mi][nj][0]=0.f; c[mi][nj][1]=0.f; c[mi][nj][2]=0.f; c[mi][nj][3]=0.f; }
    const int aoff = (32 * wr + (lane & 15)) * SBF + ((lane >> 4) << 3);
    const int boff = (32 * wc + (lane & 7) + ((lane >> 4) << 3)) * SBF + (((lane >> 3) & 1) << 3);
    #pragma unroll
    for (int kt = 0; kt < 4; kt++) {
        uint32_t ah0[4], al0[4], ah1[4], al1[4];
        ldsmx4(ah0, s2u(Ah + aoff + kt * 16));
        ldsmx4(al0, s2u(Al + aoff + kt * 16));
        ldsmx4(ah1, s2u(Ah + aoff + 16 * SBF + kt * 16));
        ldsmx4(al1, s2u(Al + aoff + 16 * SBF + kt * 16));
        #pragma unroll
        for (int np = 0; np < 2; np++) {
            uint32_t bh[4], bl[4];
            ldsmx4(bh, s2u(Bh + boff + np * 16 * SBF + kt * 16));
            ldsmx4(bl, s2u(Bl + boff + np * 16 * SBF + kt * 16));
            mma_bf16(c[0][2*np],   ah0, bh);  mma_bf16(c[0][2*np+1], ah0, bh + 2);
            mma_bf16(c[0][2*np],   al0, bh);  mma_bf16(c[0][2*np+1], al0, bh + 2);
            mma_bf16(c[0][2*np],   ah0, bl);  mma_bf16(c[0][2*np+1], ah0, bl + 2);
            mma_bf16(c[1][2*np],   ah1, bh);  mma_bf16(c[1][2*np+1], ah1, bh + 2);
            mma_bf16(c[1][2*np],   al1, bh);  mma_bf16(c[1][2*np+1], al1, bh + 2);
            mma_bf16(c[1][2*np],   ah1, bl);  mma_bf16(c[1][2*np+1], ah1, bl + 2);
        }
    }
}

// -------------------------------------------------------------- prep kernel --
__global__ void prep_kernel(const float* __restrict__ Q,
                            const float* __restrict__ K,
                            const float* __restrict__ V) {
    int i4 = blockIdx.x * 256 + threadIdx.x;
    const float* s = blockIdx.y == 0 ? Q : (blockIdx.y == 1 ? K : V);
    float4 x = ((const float4*)s)[i4];
    __nv_bfloat162 h0 = __floats2bfloat162_rn(x.x, x.y);
    __nv_bfloat162 h1 = __floats2bfloat162_rn(x.z, x.w);
    float2 f0 = __bfloat1622float2(h0);
    float2 f1 = __bfloat1622float2(h1);
    __nv_bfloat162 l0 = __floats2bfloat162_rn(x.x - f0.x, x.y - f0.y);
    __nv_bfloat162 l1 = __floats2bfloat162_rn(x.z - f1.x, x.w - f1.y);
    ((uint2*)&gH[blockIdx.y][0])[i4] = make_uint2(*(uint32_t*)&h0, *(uint32_t*)&h1);
    ((uint2*)&gL[blockIdx.y][0])[i4] = make_uint2(*(uint32_t*)&l0, *(uint32_t*)&l1);
}

// -------------------------------------------------------------- flash (mma) --
__global__ __launch_bounds__(128, 2)
void flash_mma(float* __restrict__ out)
{
    extern __shared__ __nv_bfloat16 sbf[];
    __nv_bfloat16* sQh = sbf;
    __nv_bfloat16* sQl = sbf + TSZ;
    __nv_bfloat16* strm = sbf + 2 * TSZ;

    const int t = threadIdx.x, w = t >> 5, lane = t & 31;
    const int head = blockIdx.y;
    const int row0 = blockIdx.x * 64;
    const size_t hoff = (size_t)head * LSEQ * DDIM;

    const __nv_bfloat16 *gQH = &gH[0][0], *gQL = &gL[0][0];
    const __nv_bfloat16 *gKH = &gH[1][0], *gKL = &gL[1][0];
    const __nv_bfloat16 *gVH = &gH[2][0], *gVL = &gL[2][0];

    stage_async(sQh, gQH + hoff + (size_t)row0 * DDIM, t);
    stage_async(sQl, gQL + hoff + (size_t)row0 * DDIM, t);
    CP_COMMIT();
    {
        __nv_bfloat16* b0 = strm;
        stage_async(b0,           gKH + hoff, t);
        stage_async(b0 + TSZ,     gKL + hoff, t);
        stage_async(b0 + 2 * TSZ, gVH + hoff, t);
        stage_async(b0 + 3 * TSZ, gVL + hoff, t);
    }
    CP_COMMIT();

    float o[8][4];
    #pragma unroll
    for (int nt = 0; nt < 8; nt++) { o[nt][0]=0.f; o[nt][1]=0.f; o[nt][2]=0.f; o[nt][3]=0.f; }
    float rs0 = 0.f, rs1 = 0.f;
    const int vbase = (lane & 15) * SBF + ((lane >> 4) << 3);

    for (int ch = 0; ch < LSEQ / 64; ch++) {
        if (ch + 1 < LSEQ / 64) {
            size_t coff = hoff + (size_t)(ch + 1) * 64 * DDIM;
            __nv_bfloat16* nb = strm + ((ch + 1) & 1) * 4 * TSZ;
            stage_async(nb,           gKH + coff, t);
            stage_async(nb + TSZ,     gKL + coff, t);
            stage_async(nb + 2 * TSZ, gVH + coff, t);
            stage_async(nb + 3 * TSZ, gVL + coff, t);
            CP_COMMIT(); CP_WAIT(1);
        } else CP_WAIT(0);
        __syncthreads();

        __nv_bfloat16* cb = strm + (ch & 1) * 4 * TSZ;
        __nv_bfloat16 *sKh = cb, *sKl = cb + TSZ, *sVh = cb + 2 * TSZ, *sVl = cb + 3 * TSZ;

        float c[8][4];
        gemm64(c, sQh, sQl, 16 * w, sKh, sKl, lane);

        float p[8][4];
        #pragma unroll
        for (int nt = 0; nt < 8; nt++) {
            p[nt][0] = fexp2(c[nt][0] * KEXP);
            p[nt][1] = fexp2(c[nt][1] * KEXP);
            p[nt][2] = fexp2(c[nt][2] * KEXP);
            p[nt][3] = fexp2(c[nt][3] * KEXP);
            rs0 += p[nt][0] + p[nt][1];
            rs1 += p[nt][2] + p[nt][3];
        }

        #pragma unroll
        for (int kt = 0; kt < 4; kt++) {
            uint32_t pha[4], pla[4];
            splitpack(p[2*kt][0],   p[2*kt][1],   pha[0], pla[0]);
            splitpack(p[2*kt][2],   p[2*kt][3],   pha[1], pla[1]);
            splitpack(p[2*kt+1][0], p[2*kt+1][1], pha[2], pla[2]);
            splitpack(p[2*kt+1][2], p[2*kt+1][3], pha[3], pla[3]);
            #pragma unroll
            for (int np = 0; np < 4; np++) {
                uint32_t vh[4], vl[4];
                ldsmx4t(vh, s2u(sVh + vbase + kt * 16 * SBF + np * 16));
                ldsmx4t(vl, s2u(sVl + vbase + kt * 16 * SBF + np * 16));
                mma_bf16(o[2*np],   pha, vh);  mma_bf16(o[2*np+1], pha, vh + 2);
                mma_bf16(o[2*np],   pla, vh);  mma_bf16(o[2*np+1], pla, vh + 2);
                mma_bf16(o[2*np],   pha, vl);  mma_bf16(o[2*np+1], pha, vl + 2);
            }
        }
        __syncthreads();
    }

    rs0 += __shfl_xor_sync(~0u, rs0, 1); rs0 += __shfl_xor_sync(~0u, rs0, 2);
    rs1 += __shfl_xor_sync(~0u, rs1, 1); rs1 += __shfl_xor_sync(~0u, rs1, 2);
    const float inv0 = 1.0f / rs0, inv1 = 1.0f / rs1;

    const int r0 = row0 + 16 * w + (lane >> 2);
    float* O0 = out + ((size_t)head * LSEQ + r0) * DDIM + 2 * (lane & 3);
    float* O1 = O0 + 8 * DDIM;
    #pragma unroll
    for (int nt = 0; nt < 8; nt++) {
        *(float2*)(O0 + nt * 8) = make_float2(o[nt][0] * inv0, o[nt][1] * inv0);
        *(float2*)(O1 + nt * 8) = make_float2(o[nt][2] * inv1, o[nt][3] * inv1);
    }
}

// ----------------------- weights pass 1: compute exp once ---------------------
// CTA: 128 threads, 64 rows. Streams 64-col chunks (32 Q-jobs then 32 K-jobs),
// writes exp(score) fp32 to gScr, accumulates row sums, writes 1/sum to gInv.
__global__ __launch_bounds__(128, 2)
void weights_pass1()
{
    extern __shared__ __nv_bfloat16 sb[];
    __nv_bfloat16* sAh = sb;                 // Q rows (persist)
    __nv_bfloat16* sAl = sb + TSZ;
    __nv_bfloat16* sBh = sb + 2 * TSZ;       // K rows (persist)
    __nv_bfloat16* sBl = sb + 3 * TSZ;
    __nv_bfloat16* sCh[2] = { sb + 4 * TSZ, sb + 6 * TSZ };
    __nv_bfloat16* sCl[2] = { sb + 5 * TSZ, sb + 7 * TSZ };
    float* red = (float*)(sb + 8 * TSZ);     // [64 rows][2 wc] x2 mats

    const int t = threadIdx.x, w = t >> 5, lane = t & 31;
    const int wr = w & 1, wc = w >> 1;
    const int head = blockIdx.y;
    const int row0 = blockIdx.x * 64;
    const size_t hoff = (size_t)head * LSEQ * DDIM;
    const size_t roff = hoff + (size_t)row0 * DDIM;

    const __nv_bfloat16 *gQH = &gH[0][0], *gQL = &gL[0][0];
    const __nv_bfloat16 *gKH = &gH[1][0], *gKL = &gL[1][0];

    stage_async(sAh, gQH + roff, t);
    stage_async(sAl, gQL + roff, t);
    stage_async(sBh, gKH + roff, t);
    stage_async(sBl, gKL + roff, t);
    CP_COMMIT();
    stage_async(sCh[0], gQH + hoff, t);
    stage_async(sCl[0], gQL + hoff, t);
    CP_COMMIT();

    float sq[2][2] = {{0.f,0.f},{0.f,0.f}}, sk[2][2] = {{0.f,0.f},{0.f,0.f}};
    const int colb = 32 * wc + 2 * (lane & 3);
    const size_t scrRow = (size_t)head * LSEQ + row0;

    for (int j = 0; j < 64; j++) {
        int jn = j + 1;
        if (jn < 64) {
            size_t off = hoff + (size_t)(jn & 31) * 64 * DDIM;
            stage_async(sCh[jn & 1], (jn < 32 ? gQH : gKH) + off, t);
            stage_async(sCl[jn & 1], (jn < 32 ? gQL : gKL) + off, t);
            CP_COMMIT(); CP_WAIT(1);
        } else CP_WAIT(0);
        __syncthreads();

        const int mat = j >> 5;              // 0 = Q, 1 = K
        const int ch = j & 31;
        float c[2][4][4];
        gemm32(c, mat ? sBh : sAh, mat ? sBl : sAl, wr, sCh[j & 1], sCl[j & 1], wc, lane);

        float* Sc = &gScr[mat][0];
        #pragma unroll
        for (int mi = 0; mi < 2; mi++) {
            size_t r_ = scrRow + 32 * wr + 16 * mi + (lane >> 2);
            float* W0 = Sc + r_ * LSEQ + ch * 64 + colb;
            float* W1 = W0 + 8 * LSEQ;
            float acc0 = 0.f, acc1 = 0.f;
            #pragma unroll
            for (int nj = 0; nj < 4; nj++) {
                float e0 = fexp2(c[mi][nj][0] * KEXP);
                float e1 = fexp2(c[mi][nj][1] * KEXP);
                float e2 = fexp2(c[mi][nj][2] * KEXP);
                float e3 = fexp2(c[mi][nj][3] * KEXP);
                acc0 += e0 + e1;
                acc1 += e2 + e3;
                *(float2*)(W0 + 8 * nj) = make_float2(e0, e1);
                *(float2*)(W1 + 8 * nj) = make_float2(e2, e3);
            }
            if (mat == 0) { sq[mi][0] += acc0; sq[mi][1] += acc1; }
            else          { sk[mi][0] += acc0; sk[mi][1] += acc1; }
        }
        __syncthreads();
    }

    // reduce sums: quad shuffle (cols within warp), cross-warp (wc) via smem
    #pragma unroll
    for (int mi = 0; mi < 2; mi++)
        #pragma unroll
        for (int b = 0; b < 2; b++) {
            float x = sq[mi][b];
            x += __shfl_xor_sync(~0u, x, 1); x += __shfl_xor_sync(~0u, x, 2);
            sq[mi][b] = x;
            float y = sk[mi][b];
            y += __shfl_xor_sync(~0u, y, 1); y += __shfl_xor_sync(~0u, y, 2);
            sk[mi][b] = y;
        }
    if ((lane & 3) == 0) {
        #pragma unroll
        for (int mi = 0; mi < 2; mi++)
            #pragma unroll
            for (int b = 0; b < 2; b++) {
                int rl = 32 * wr + 16 * mi + (lane >> 2) + 8 * b;
                red[rl * 2 + wc]       = sq[mi][b];
                red[128 + rl * 2 + wc] = sk[mi][b];
            }
    }
    __syncthreads();
    // two warps cover the 64 rows; write 1/sum
    if (t < 64) {
        gInv[0][scrRow + t] = 1.0f / (red[t * 2] + red[t * 2 + 1]);
        gInv[1][scrRow + t] = 1.0f / (red[128 + t * 2] + red[128 + t * 2 + 1]);
    }
}

// ----------------------- weights pass 2: scale + add (bandwidth) --------------
__global__ __launch_bounds__(256)
void weights_pass2(float* __restrict__ outw)
{
    size_t i4 = (size_t)blockIdx.x * 256 + threadIdx.x;     // float4 index
    size_t row = (i4 * 4) >> 11;                            // global row (head*2048+r)
    float invq = gInv[0][row];
    float invk = gInv[1][row];
    float4 q = ((const float4*)&gScr[0][0])[i4];
    float4 k = ((const float4*)&gScr[1][0])[i4];
    float4 o;
    o.x = q.x * invq + k.x * invk;
    o.y = q.y * invq + k.y * invk;
    o.z = q.z * invq + k.z * invk;
    o.w = q.w * invq + k.w * invk;
    ((float4*)outw)[i4] = o;
}

// ------------------------------------------------------------------ launcher --
extern "C" void kernel_launch(void* const* d_in, const int* in_sizes, int n_in,
                              void* d_out, int out_size) {
    const float* Q = (const float*)d_in[0];
    const float* K = (const float*)d_in[1];
    const float* V = (const float*)d_in[2];
    float* out = (float*)d_out;

    const int F_SMEM = 10 * TSZ * 2;                 // 92,160 B
    const int W_SMEM = 8 * TSZ * 2 + 256 * 4;        // 74,752 B

    cudaFuncSetAttribute(flash_mma,     cudaFuncAttributeMaxDynamicSharedMemorySize, F_SMEM);
    cudaFuncSetAttribute(weights_pass1, cudaFuncAttributeMaxDynamicSharedMemorySize, W_SMEM);

    prep_kernel<<<dim3(NELEM / 1024, 3), 256>>>(Q, K, V);
    flash_mma<<<dim3(LSEQ / 64, BH), 128, F_SMEM>>>(out);

    const size_t outElems  = (size_t)NELEM;
    const size_t attnElems = (size_t)ATTN;
    if ((size_t)out_size >= outElems + attnElems) {
        weights_pass1<<<dim3(LSEQ / 64, BH), 128, W_SMEM>>>();
        weights_pass2<<<ATTN / (4 * 256), 256>>>(out + outElems);
    }
}